// round 3
// baseline (speedup 1.0000x reference)
#include <cuda_runtime.h>

#define NN 100000
#define NF 512
#define NH 16
#define NC 40
#define NE 3200000

// Scratch (no allocations allowed -> __device__ globals)
__device__ float g_dinv[NN];          // degree, then rsqrt(degree)
__device__ float g_feat[NN * NH];     // pre-scaled features (message payload)
__device__ float g_agg[NN * NH];      // aggregation accumulator

// ---------------------------------------------------------------- degree
__global__ void k_deg_init() {
    int i = blockIdx.x * blockDim.x + threadIdx.x;
    if (i < NN) g_dinv[i] = 1.0f;   // self-loop
}

__global__ void k_deg_count(const int* __restrict__ dst) {
    int e = blockIdx.x * blockDim.x + threadIdx.x;
    if (e < NE) atomicAdd(&g_dinv[dst[e]], 1.0f);  // exact integer-valued float adds
}

__global__ void k_rsqrt() {
    int i = blockIdx.x * blockDim.x + threadIdx.x;
    if (i < NN) g_dinv[i] = rsqrtf(g_dinv[i]);
}

// ---------------------------------------------------------------- GEMM1: h = (x @ W1) * dinv
// 256 threads, 256 nodes per block. x staged in shared (coalesced), W broadcast
// via LDS.64, packed f32x2 FMAs over k-pairs.
__global__ __launch_bounds__(256) void k_gemm1(const float* __restrict__ x,
                                               const float* __restrict__ W1) {
    __shared__ float Ws[NF * NH];     // 32 KB
    __shared__ float xs[256 * 9];     // 8-col chunk, pad to 9 (conflict-free)
    const int tid = threadIdx.x;
    const int base = blockIdx.x * 256;
    const int node = base + tid;

    for (int i = tid; i < NF * NH; i += 256) Ws[i] = W1[i];
    const unsigned long long* Ws2 = reinterpret_cast<const unsigned long long*>(Ws);

    unsigned long long acc[8];
#pragma unroll
    for (int j = 0; j < 8; j++) acc[j] = 0ull;

    for (int cb = 0; cb < NF; cb += 8) {
        __syncthreads();
        // stage 256 nodes x 8 cols, coalesced
#pragma unroll
        for (int j = 0; j < 8; j++) {
            int i = tid + j * 256;          // [0, 2048)
            int n = i >> 3, c = i & 7;
            int gn = base + n;
            xs[n * 9 + c] = (gn < NN) ? x[(size_t)gn * NF + cb + c] : 0.0f;
        }
        __syncthreads();
#pragma unroll
        for (int c = 0; c < 8; c++) {
            unsigned xu = __float_as_uint(xs[tid * 9 + c]);
            unsigned long long x2;
            asm("mov.b64 %0, {%1, %1};" : "=l"(x2) : "r"(xu));
#pragma unroll
            for (int j = 0; j < 8; j++) {
                unsigned long long w2 = Ws2[(cb + c) * 8 + j];  // broadcast
                asm("fma.rn.f32x2 %0, %1, %2, %0;" : "+l"(acc[j]) : "l"(x2), "l"(w2));
            }
        }
    }

    if (node < NN) {
        float dv = g_dinv[node];
        float o[16];
#pragma unroll
        for (int j = 0; j < 8; j++) {
            unsigned lo, hi;
            asm("mov.b64 {%0, %1}, %2;" : "=r"(lo), "=r"(hi) : "l"(acc[j]));
            o[2 * j]     = __uint_as_float(lo) * dv;
            o[2 * j + 1] = __uint_as_float(hi) * dv;
        }
        float4* f = (float4*)(g_feat + (size_t)node * NH);
        float4* a = (float4*)(g_agg  + (size_t)node * NH);
#pragma unroll
        for (int q = 0; q < 4; q++) {
            float4 v = make_float4(o[4*q], o[4*q+1], o[4*q+2], o[4*q+3]);
            f[q] = v;
            a[q] = v;   // self-loop contribution (pre-scaled)
        }
    }
}

// ---------------------------------------------------------------- edge scatter: agg[dst] += feat[src]
__device__ __forceinline__ void red_add_v4(float* p, float4 v) {
    asm volatile("red.global.add.v4.f32 [%0], {%1,%2,%3,%4};"
                 :: "l"(p), "f"(v.x), "f"(v.y), "f"(v.z), "f"(v.w) : "memory");
}

__global__ void k_scatter(const int* __restrict__ src, const int* __restrict__ dst) {
    int e = blockIdx.x * blockDim.x + threadIdx.x;
    if (e >= NE) return;
    int s = src[e], d = dst[e];
    const float4* h = (const float4*)(g_feat + (size_t)s * NH);
    float4 a = h[0], b = h[1], c = h[2], w = h[3];
    float* o = g_agg + (size_t)d * NH;
    red_add_v4(o,      a);
    red_add_v4(o + 4,  b);
    red_add_v4(o + 8,  c);
    red_add_v4(o + 12, w);
}

// ---------------------------------------------------------------- mid: g = relu(dinv*agg + b1) * dinv
__global__ void k_mid(const float* __restrict__ b1) {
    int i = blockIdx.x * blockDim.x + threadIdx.x;
    if (i >= NN) return;
    float dv = g_dinv[i];
    float4* a = (float4*)(g_agg  + (size_t)i * NH);
    float4* f = (float4*)(g_feat + (size_t)i * NH);
#pragma unroll
    for (int q = 0; q < 4; q++) {
        float4 v = a[q];
        float4 w;
        w.x = fmaxf(fmaf(v.x, dv, __ldg(b1 + 4*q + 0)), 0.f) * dv;
        w.y = fmaxf(fmaf(v.y, dv, __ldg(b1 + 4*q + 1)), 0.f) * dv;
        w.z = fmaxf(fmaf(v.z, dv, __ldg(b1 + 4*q + 2)), 0.f) * dv;
        w.w = fmaxf(fmaf(v.w, dv, __ldg(b1 + 4*q + 3)), 0.f) * dv;
        f[q] = w;       // message payload for layer 2
        a[q] = w;       // self-loop init for layer-2 accumulator
    }
}

// ---------------------------------------------------------------- out: log_softmax(dinv*agg @ W2 + b2)
__global__ __launch_bounds__(256) void k_out(const float* __restrict__ W2,
                                             const float* __restrict__ b2,
                                             float* __restrict__ out) {
    __shared__ float Ws[NH * NC];   // 2.5 KB
    __shared__ float bs[NC];
    int tid = threadIdx.x;
    for (int i = tid; i < NH * NC; i += 256) Ws[i] = W2[i];
    if (tid < NC) bs[tid] = b2[tid];
    __syncthreads();

    int i = blockIdx.x * 256 + tid;
    if (i >= NN) return;
    float dv = g_dinv[i];

    float v[NH];
    const float4* a = (const float4*)(g_agg + (size_t)i * NH);
#pragma unroll
    for (int q = 0; q < 4; q++) {
        float4 t = a[q];
        v[4*q+0] = t.x * dv; v[4*q+1] = t.y * dv;
        v[4*q+2] = t.z * dv; v[4*q+3] = t.w * dv;
    }

    float o[NC];
    float m = -1e30f;
#pragma unroll
    for (int k = 0; k < NC; k++) {
        float s = bs[k];
#pragma unroll
        for (int j = 0; j < NH; j++) s = fmaf(v[j], Ws[j * NC + k], s);
        o[k] = s;
        m = fmaxf(m, s);
    }
    float sum = 0.f;
#pragma unroll
    for (int k = 0; k < NC; k++) sum += __expf(o[k] - m);
    float l = m + logf(sum);

    float4* op = (float4*)(out + (size_t)i * NC);
#pragma unroll
    for (int q = 0; q < 10; q++) {
        op[q] = make_float4(o[4*q] - l, o[4*q+1] - l, o[4*q+2] - l, o[4*q+3] - l);
    }
}

// ----------------------------------------------------------------
extern "C" void kernel_launch(void* const* d_in, const int* in_sizes, int n_in,
                              void* d_out, int out_size) {
    const float* x  = (const float*)d_in[0];
    const int*   ei = (const int*)d_in[1];
    const float* W1 = (const float*)d_in[2];
    const float* b1 = (const float*)d_in[3];
    const float* W2 = (const float*)d_in[4];
    const float* b2 = (const float*)d_in[5];
    float* out = (float*)d_out;

    const int* src = ei;        // edge_index[0]
    const int* dst = ei + NE;   // edge_index[1]

    const int NB_N = (NN + 255) / 256;   // 391
    const int NB_E = (NE + 255) / 256;   // 12500

    k_deg_init<<<NB_N, 256>>>();
    k_deg_count<<<NB_E, 256>>>(dst);
    k_rsqrt<<<NB_N, 256>>>();
    k_gemm1<<<NB_N, 256>>>(x, W1);
    k_scatter<<<NB_E, 256>>>(src, dst);
    k_mid<<<NB_N, 256>>>(b1);
    k_scatter<<<NB_E, 256>>>(src, dst);
    k_out<<<NB_N, 256>>>(W2, b2, out);
}